// round 16
// baseline (speedup 1.0000x reference)
#include <cuda_runtime.h>
#include <cuda_bf16.h>
#include <cstdint>

// Problem constants (fixed by the reference)
#define N_LIG   100000
#define N_TGT   20000
#define N_EDGE  250000
#define LIG_IN  4
#define TGT_IN  1280
#define HID     128
#define ZCOLS   256           // [y_t (W_tl_l) | z_r (W_lt_r)]

#define MROWS   96            // M-tile rows (2 x 48)
#define MTILES  209           // ceil(20000 / 96)
#define N_TGT_PAD 20096       // >= 209*96 = 20064

#define SCAN_B 256
#define NBLK ((N_LIG + SCAN_B - 1) / SCAN_B)   // 391

// ---------------- scratch (device globals; no allocation allowed) ----------
__device__ float g_accT[N_TGT * LIG_IN];
__device__ int   g_cntLi[N_LIG];
__device__ int   g_cntTi[N_TGT];
__device__ int   g_offL[N_LIG];
__device__ int   g_woff[N_LIG];
__device__ int   g_part[NBLK];
__device__ int   g_elist[N_EDGE];
__device__ float g_z[(size_t)N_TGT_PAD * ZCOLS];   // fused target projection
__device__ __nv_bfloat16 g_Bh[ZCOLS * TGT_IN];     // [n][k] hi part
__device__ __nv_bfloat16 g_Bl[ZCOLS * TGT_IN];     // [n][k] lo part
__device__ float g_sl[N_LIG];
__device__ float g_st[N_TGT];

// =================== helpers =================================================
static __device__ __forceinline__ uint32_t smem_u32(const void* p) {
    uint32_t a;
    asm("{ .reg .u64 t; cvta.to.shared.u64 t, %1; cvt.u32.u64 %0, t; }"
        : "=r"(a) : "l"(p));
    return a;
}

static __device__ __forceinline__ void ldmx4(uint32_t* r, uint32_t addr) {
    asm volatile("ldmatrix.sync.aligned.m8n8.x4.shared.b16 {%0,%1,%2,%3}, [%4];"
                 : "=r"(r[0]), "=r"(r[1]), "=r"(r[2]), "=r"(r[3]) : "r"(addr));
}

static __device__ __forceinline__ void mma16816(float* d, const uint32_t* a,
                                                uint32_t b0, uint32_t b1) {
    asm volatile(
        "mma.sync.aligned.m16n8k16.row.col.f32.bf16.bf16.f32 "
        "{%0,%1,%2,%3}, {%4,%5,%6,%7}, {%8,%9}, {%0,%1,%2,%3};"
        : "+f"(d[0]), "+f"(d[1]), "+f"(d[2]), "+f"(d[3])
        : "r"(a[0]), "r"(a[1]), "r"(a[2]), "r"(a[3]), "r"(b0), "r"(b1));
}

static __device__ __forceinline__ void cp16(uint32_t saddr, const void* gaddr) {
    asm volatile("cp.async.cg.shared.global [%0], [%1], 16;"
                 :: "r"(saddr), "l"(gaddr));
}

// ============ W split kernel: g_Bh/g_Bl[n][k] from W_tl_l / W_lt_r =========
__global__ void conv_w_kernel(const float* __restrict__ W_tl_l,
                              const float* __restrict__ W_lt_r) {
    int idx = blockIdx.x * blockDim.x + threadIdx.x;
    if (idx >= ZCOLS * TGT_IN) return;
    int n = idx / TGT_IN;
    int k = idx % TGT_IN;
    float w = (n < HID) ? W_tl_l[k * HID + n] : W_lt_r[k * HID + (n - HID)];
    __nv_bfloat16 h = __float2bfloat16_rn(w);
    __nv_bfloat16 l = __float2bfloat16_rn(w - __bfloat162float(h));
    g_Bh[idx] = h;
    g_Bl[idx] = l;
}

// ============ edge light pass: degree histograms + target accumulators ======
__global__ __launch_bounds__(256) void edge_light_kernel(
    const int* __restrict__ esrc, const int* __restrict__ edst,
    const float* __restrict__ xlig) {
    int e = blockIdx.x * blockDim.x + threadIdx.x;
    if (e >= N_EDGE) return;
    int s = esrc[e];
    int d = edst[e];
    atomicAdd(&g_cntLi[s], 1);
    atomicAdd(&g_cntTi[d], 1);
    float4 xf = *(const float4*)(xlig + (size_t)s * LIG_IN);
    float* t = g_accT + (size_t)d * LIG_IN;
    atomicAdd(t + 0, xf.x); atomicAdd(t + 1, xf.y);
    atomicAdd(t + 2, xf.z); atomicAdd(t + 3, xf.w);
}

// ============ exclusive scan over g_cntLi -> g_offL (3 kernels) =============
__global__ __launch_bounds__(SCAN_B) void scan1_kernel() {
    __shared__ int sm[SCAN_B];
    int i = blockIdx.x * SCAN_B + threadIdx.x;
    int v = (i < N_LIG) ? g_cntLi[i] : 0;
    sm[threadIdx.x] = v;
    __syncthreads();
    int incl = v;
    #pragma unroll
    for (int o = 1; o < SCAN_B; o <<= 1) {
        int u = (threadIdx.x >= o) ? sm[threadIdx.x - o] : 0;
        __syncthreads();
        incl += u;
        sm[threadIdx.x] = incl;
        __syncthreads();
    }
    if (i < N_LIG) g_offL[i] = incl - v;
    if (threadIdx.x == SCAN_B - 1) g_part[blockIdx.x] = incl;
}

__global__ __launch_bounds__(512) void scan2_kernel() {
    __shared__ int sm[512];
    int t = threadIdx.x;
    int v = (t < NBLK) ? g_part[t] : 0;
    sm[t] = v;
    __syncthreads();
    int incl = v;
    #pragma unroll
    for (int o = 1; o < 512; o <<= 1) {
        int u = (t >= o) ? sm[t - o] : 0;
        __syncthreads();
        incl += u;
        sm[t] = incl;
        __syncthreads();
    }
    if (t < NBLK) g_part[t] = incl - v;   // exclusive
}

__global__ __launch_bounds__(SCAN_B) void scan3_kernel() {
    int i = blockIdx.x * SCAN_B + threadIdx.x;
    if (i >= N_LIG) return;
    int off = g_offL[i] + g_part[blockIdx.x];
    g_offL[i] = off;
    g_woff[i] = off;
}

// ============ fill edge lists ==============================================
__global__ __launch_bounds__(256) void fill_kernel(
    const int* __restrict__ esrc, const int* __restrict__ edst) {
    int e = blockIdx.x * blockDim.x + threadIdx.x;
    if (e >= N_EDGE) return;
    int pos = atomicAdd(&g_woff[esrc[e]], 1);
    g_elist[pos] = edst[e];
}

// ============ bf16 HMMA GEMM: z = split(x_target) @ split(W)^T ==============
// Block 96x128, BK=32, 256 thr, 8 warps (2 m-rows x 4 n-cols), warp 48x32.
// 3-product split: Ah*Bh + Ah*Bl + Al*Bh, fp32 accumulate (R4/R6 math,
// M=96 balanced tiling). ldmatrix fragments, A+B double-buffered, 2 CTAs/SM.
#define GKCH 40                 // 1280 / 32
#define APITCH 80               // bytes per 32-bf16 row (pad kills conflicts)
#define A_PART 7680             // 96 * 80
#define ABUF_STRIDE 15360       // hi + lo
#define OFF_B 30720
#define B_PART 10240            // 128 * 80
#define BSTG_STRIDE 20480       // hi + lo
#define GSM_TOT (OFF_B + 2 * BSTG_STRIDE)   // 71680

__global__ void __launch_bounds__(256, 2) gemm_mma_kernel(
    const float* __restrict__ X,
    const __nv_bfloat16* __restrict__ Bh,
    const __nv_bfloat16* __restrict__ Bl) {
    extern __shared__ char smem[];
    const uint32_t sb = smem_u32(smem);
    const int tid = threadIdx.x;
    const int lane = tid & 31;
    const int wid = tid >> 5;
    const int warpRow = wid & 1;      // m: 2 x 48
    const int warpCol = wid >> 1;     // n: 4 x 32

    // ---- A producer: threads 0..191, 2 threads per row, 16 floats each ----
    const bool aact = tid < 2 * MROWS;
    const int arow = tid >> 1;
    const int ahalf = tid & 1;
    const long growA = (long)blockIdx.y * MROWS + arow;
    const bool aval = aact && (growA < N_TGT);
    const float* aptr = X + (size_t)(aval ? growA : 0) * TGT_IN + ahalf * 16;
    const uint32_t a_off = (uint32_t)(arow * APITCH + ahalf * 32);

    // ---- B producer: 2 threads per n-row, 16 bf16 each ----
    const int brow = tid >> 1;
    const int bhalf = tid & 1;
    const size_t boffg = (size_t)(blockIdx.x * 128 + brow) * TGT_IN + bhalf * 16;
    const __nv_bfloat16* bhp = Bh + boffg;
    const __nv_bfloat16* blp = Bl + boffg;
    const uint32_t b_sts = (uint32_t)(brow * APITCH + bhalf * 32);

    // ---- ldmatrix lane addressing (relative) ----
    const uint32_t a_lm =
        (uint32_t)((warpRow * 48 + (lane & 15)) * APITCH + (lane >> 4) * 16);
    const uint32_t b_lm =
        (uint32_t)((warpCol * 32 + ((lane >> 4) & 1) * 8 + (lane & 7)) * APITCH
                   + ((lane >> 3) & 1) * 16);

    float acc[3][4][4];
    #pragma unroll
    for (int i = 0; i < 3; i++)
        #pragma unroll
        for (int j = 0; j < 4; j++)
            #pragma unroll
            for (int q = 0; q < 4; q++) acc[i][j][q] = 0.f;

    float4 apre[4];

    auto storeA = [&](int buf) {
        float f[16] = {apre[0].x, apre[0].y, apre[0].z, apre[0].w,
                       apre[1].x, apre[1].y, apre[1].z, apre[1].w,
                       apre[2].x, apre[2].y, apre[2].z, apre[2].w,
                       apre[3].x, apre[3].y, apre[3].z, apre[3].w};
        uint32_t hi[8], lo[8];
        #pragma unroll
        for (int j = 0; j < 8; j++) {
            __nv_bfloat16 h0 = __float2bfloat16_rn(f[2 * j]);
            __nv_bfloat16 h1 = __float2bfloat16_rn(f[2 * j + 1]);
            __nv_bfloat16 l0 = __float2bfloat16_rn(f[2 * j] - __bfloat162float(h0));
            __nv_bfloat16 l1 = __float2bfloat16_rn(f[2 * j + 1] - __bfloat162float(h1));
            __nv_bfloat162 hp = __halves2bfloat162(h0, h1);
            __nv_bfloat162 lp = __halves2bfloat162(l0, l1);
            hi[j] = *reinterpret_cast<uint32_t*>(&hp);
            lo[j] = *reinterpret_cast<uint32_t*>(&lp);
        }
        char* base = smem + buf * ABUF_STRIDE + a_off;
        *(uint4*)(base) = make_uint4(hi[0], hi[1], hi[2], hi[3]);
        *(uint4*)(base + 16) = make_uint4(hi[4], hi[5], hi[6], hi[7]);
        *(uint4*)(base + A_PART) = make_uint4(lo[0], lo[1], lo[2], lo[3]);
        *(uint4*)(base + A_PART + 16) = make_uint4(lo[4], lo[5], lo[6], lo[7]);
    };

    // ---------- prologue: chunk 0 ----------
    {
        uint32_t s0 = sb + OFF_B;
        #pragma unroll
        for (int j = 0; j < 2; j++) {
            cp16(s0 + b_sts + j * 16, bhp + j * 8);
            cp16(s0 + B_PART + b_sts + j * 16, blp + j * 8);
        }
        asm volatile("cp.async.commit_group;");
        if (aval) {
            #pragma unroll
            for (int i = 0; i < 4; i++)
                apre[i] = *(const float4*)(aptr + i * 4);
        } else {
            #pragma unroll
            for (int i = 0; i < 4; i++) apre[i] = make_float4(0.f, 0.f, 0.f, 0.f);
        }
        if (aact) storeA(0);
        asm volatile("cp.async.wait_group 0;");
        __syncthreads();
    }

    // ---------- main loop: one sync per chunk ----------
    for (int c = 0; c < GKCH; c++) {
        const bool more = (c + 1) < GKCH;
        if (more) {
            uint32_t snext = sb + OFF_B + ((c + 1) & 1) * BSTG_STRIDE;
            const __nv_bfloat16* bh2 = bhp + (c + 1) * 32;
            const __nv_bfloat16* bl2 = blp + (c + 1) * 32;
            #pragma unroll
            for (int j = 0; j < 2; j++) {
                cp16(snext + b_sts + j * 16, bh2 + j * 8);
                cp16(snext + B_PART + b_sts + j * 16, bl2 + j * 8);
            }
            asm volatile("cp.async.commit_group;");
            if (aval) {
                #pragma unroll
                for (int i = 0; i < 4; i++)
                    apre[i] = *(const float4*)(aptr + (c + 1) * 32 + i * 4);
            }
        }

        // ---- compute on chunk c ----
        {
            const uint32_t abase = sb + (c & 1) * ABUF_STRIDE;
            const uint32_t bstage = sb + OFF_B + (c & 1) * BSTG_STRIDE;
            #pragma unroll
            for (int ks = 0; ks < 2; ks++) {
                uint32_t bhf[2][4], blf[2][4];
                #pragma unroll
                for (int ntp = 0; ntp < 2; ntp++) {
                    ldmx4(bhf[ntp], bstage + b_lm + ntp * (16 * APITCH) + ks * 32);
                    ldmx4(blf[ntp], bstage + B_PART + b_lm + ntp * (16 * APITCH) + ks * 32);
                }
                #pragma unroll
                for (int mt = 0; mt < 3; mt++) {
                    uint32_t ah[4], al[4];
                    ldmx4(ah, abase + a_lm + mt * (16 * APITCH) + ks * 32);
                    ldmx4(al, abase + A_PART + a_lm + mt * (16 * APITCH) + ks * 32);
                    #pragma unroll
                    for (int nt = 0; nt < 4; nt++) {
                        uint32_t b0h = bhf[nt >> 1][(nt & 1) * 2];
                        uint32_t b1h = bhf[nt >> 1][(nt & 1) * 2 + 1];
                        mma16816(acc[mt][nt], ah, b0h, b1h);
                        mma16816(acc[mt][nt], ah,
                                 blf[nt >> 1][(nt & 1) * 2],
                                 blf[nt >> 1][(nt & 1) * 2 + 1]);
                        mma16816(acc[mt][nt], al, b0h, b1h);
                    }
                }
            }
        }

        if (more) {
            if (aact) storeA((c + 1) & 1);       // writes the OTHER A buffer
            asm volatile("cp.async.wait_group 0;");
        }
        __syncthreads();
    }

    // ---------- epilogue: write fp32 accumulators to g_z ----------
    const int rbase = blockIdx.y * MROWS + warpRow * 48;
    const int cbase = blockIdx.x * 128 + warpCol * 32;
    #pragma unroll
    for (int mt = 0; mt < 3; mt++) {
        #pragma unroll
        for (int nt = 0; nt < 4; nt++) {
            int r0 = rbase + mt * 16 + (lane >> 2);
            int cc = cbase + nt * 8 + (lane & 3) * 2;
            *(float2*)(g_z + (size_t)r0 * ZCOLS + cc) =
                make_float2(acc[mt][nt][0], acc[mt][nt][1]);
            *(float2*)(g_z + (size_t)(r0 + 8) * ZCOLS + cc) =
                make_float2(acc[mt][nt][2], acc[mt][nt][3]);
        }
    }
}

// ---------------- target finalize: s_t[t] = <relu(t_out), W_ep[128:256]> ---
__global__ __launch_bounds__(256) void target_final_kernel(
    const float* __restrict__ W_lt_l, const float* __restrict__ b_lt_l,
    const float* __restrict__ W_ep) {
    int t = blockIdx.x * (blockDim.x >> 5) + (threadIdx.x >> 5);
    int lane = threadIdx.x & 31;
    if (t >= N_TGT) return;
    float inv = 1.f / fmaxf((float)g_cntTi[t], 1.f);
    float m0 = g_accT[t * 4 + 0] * inv;
    float m1 = g_accT[t * 4 + 1] * inv;
    float m2 = g_accT[t * 4 + 2] * inv;
    float m3 = g_accT[t * 4 + 3] * inv;
    float sum = 0.f;
    #pragma unroll
    for (int i = 0; i < 4; i++) {
        int h = lane + 32 * i;
        float v = b_lt_l[h] + g_z[(size_t)t * ZCOLS + HID + h];
        v = fmaf(m0, W_lt_l[0 * HID + h], v);
        v = fmaf(m1, W_lt_l[1 * HID + h], v);
        v = fmaf(m2, W_lt_l[2 * HID + h], v);
        v = fmaf(m3, W_lt_l[3 * HID + h], v);
        v = fmaxf(v, 0.f);
        sum = fmaf(v, W_ep[HID + h], sum);
    }
    #pragma unroll
    for (int o = 16; o > 0; o >>= 1) sum += __shfl_xor_sync(0xffffffffu, sum, o);
    if (lane == 0) g_st[t] = sum;
}

// ---------------- ligand gather + finalize (warp per ligand) ----------------
__global__ __launch_bounds__(256) void ligand_gather_kernel(
    const float* __restrict__ xlig, const float* __restrict__ W_tl_r,
    const float* __restrict__ b_tl_l, const float* __restrict__ W_ep) {
    int l = blockIdx.x * (blockDim.x >> 5) + (threadIdx.x >> 5);
    int lane = threadIdx.x & 31;
    if (l >= N_LIG) return;
    int start = g_offL[l];
    int cnt = g_cntLi[l];
    float4 acc = make_float4(0.f, 0.f, 0.f, 0.f);
    int dnext = (cnt > 0) ? g_elist[start] : 0;
    for (int i = 0; i < cnt; i++) {
        int d = dnext;
        if (i + 1 < cnt) dnext = g_elist[start + i + 1];
        float4 y = *((const float4*)(g_z + (size_t)d * ZCOLS) + lane);
        acc.x += y.x; acc.y += y.y; acc.z += y.z; acc.w += y.w;
    }
    float inv = 1.f / fmaxf((float)cnt, 1.f);
    float4 xf = *(const float4*)(xlig + (size_t)l * LIG_IN);
    float m[4] = {acc.x * inv, acc.y * inv, acc.z * inv, acc.w * inv};
    float sum = 0.f;
    #pragma unroll
    for (int j = 0; j < 4; j++) {
        int h = lane * 4 + j;
        float v = b_tl_l[h] + m[j];
        v = fmaf(xf.x, W_tl_r[0 * HID + h], v);
        v = fmaf(xf.y, W_tl_r[1 * HID + h], v);
        v = fmaf(xf.z, W_tl_r[2 * HID + h], v);
        v = fmaf(xf.w, W_tl_r[3 * HID + h], v);
        v = fmaxf(v, 0.f);
        sum = fmaf(v, W_ep[h], sum);
    }
    #pragma unroll
    for (int o = 16; o > 0; o >>= 1) sum += __shfl_xor_sync(0xffffffffu, sum, o);
    if (lane == 0) g_sl[l] = sum;
}

// ---------------- edge output ------------------------------------------------
__global__ __launch_bounds__(256) void edge_out_kernel(
    const int* __restrict__ esrc, const int* __restrict__ edst,
    const float* __restrict__ b_ep, float* __restrict__ out) {
    int e = blockIdx.x * blockDim.x + threadIdx.x;
    if (e >= N_EDGE) return;
    out[e] = g_sl[esrc[e]] + g_st[edst[e]] + b_ep[0];
}

// ---------------- launch: fork/join across two streams ----------------------
extern "C" void kernel_launch(void* const* d_in, const int* in_sizes, int n_in,
                              void* d_out, int out_size) {
    const float* x_ligand = (const float*)d_in[0];
    const float* x_target = (const float*)d_in[1];
    const int*   edge_src = (const int*)d_in[2];
    const int*   edge_dst = (const int*)d_in[3];
    const float* W_lt_l   = (const float*)d_in[4];
    const float* b_lt_l   = (const float*)d_in[5];
    const float* W_lt_r   = (const float*)d_in[6];
    const float* W_tl_l   = (const float*)d_in[7];
    const float* b_tl_l   = (const float*)d_in[8];
    const float* W_tl_r   = (const float*)d_in[9];
    const float* W_ep     = (const float*)d_in[10];
    const float* b_ep     = (const float*)d_in[11];
    float* out = (float*)d_out;

    // one-time host resources (streams/events are not device memory)
    static cudaStream_t s1 = nullptr;
    static cudaEvent_t evRoot = nullptr, evG = nullptr, ev1 = nullptr, ev2 = nullptr;
    if (!s1) {
        cudaStreamCreateWithFlags(&s1, cudaStreamNonBlocking);
        cudaEventCreateWithFlags(&evRoot, cudaEventDisableTiming);
        cudaEventCreateWithFlags(&evG, cudaEventDisableTiming);
        cudaEventCreateWithFlags(&ev1, cudaEventDisableTiming);
        cudaEventCreateWithFlags(&ev2, cudaEventDisableTiming);
    }
    cudaStream_t s0 = 0;   // capturing (legacy) stream

    // ---- fork s1 off the captured stream ----
    cudaEventRecord(evRoot, s0);
    cudaStreamWaitEvent(s1, evRoot, 0);

    // ---- s1: memsets + edge-prep head ----
    {
        void *pAccT, *pCntLi, *pCntTi;
        cudaGetSymbolAddress(&pAccT, g_accT);
        cudaGetSymbolAddress(&pCntLi, g_cntLi);
        cudaGetSymbolAddress(&pCntTi, g_cntTi);
        cudaMemsetAsync(pAccT, 0, (size_t)N_TGT * LIG_IN * sizeof(float), s1);
        cudaMemsetAsync(pCntLi, 0, (size_t)N_LIG * sizeof(int), s1);
        cudaMemsetAsync(pCntTi, 0, (size_t)N_TGT * sizeof(int), s1);
    }

    // s0: W split + GEMM
    edge_light_kernel<<<(N_EDGE + 255) / 256, 256, 0, s1>>>(edge_src, edge_dst, x_ligand);
    conv_w_kernel<<<(ZCOLS * TGT_IN + 255) / 256, 256, 0, s0>>>(W_tl_l, W_lt_r);
    {
        __nv_bfloat16* bh; cudaGetSymbolAddress((void**)&bh, g_Bh);
        __nv_bfloat16* bl; cudaGetSymbolAddress((void**)&bl, g_Bl);
        cudaFuncSetAttribute(gemm_mma_kernel,
                             cudaFuncAttributeMaxDynamicSharedMemorySize, GSM_TOT);
        dim3 grid(2, MTILES);
        gemm_mma_kernel<<<grid, 256, GSM_TOT, s0>>>(x_target, bh, bl);
    }
    cudaEventRecord(evG, s0);       // g_z ready

    // ---- s1: rest of CSR pipeline (concurrent with GEMM) ----
    scan1_kernel<<<NBLK, SCAN_B, 0, s1>>>();
    scan2_kernel<<<1, 512, 0, s1>>>();
    scan3_kernel<<<NBLK, SCAN_B, 0, s1>>>();
    fill_kernel<<<(N_EDGE + 255) / 256, 256, 0, s1>>>(edge_src, edge_dst);
    cudaEventRecord(ev1, s1);       // CSR + accT ready

    // s1: target_final needs g_z (evG) and its own accT (program order)
    cudaStreamWaitEvent(s1, evG, 0);
    target_final_kernel<<<(N_TGT + 7) / 8, 256, 0, s1>>>(W_lt_l, b_lt_l, W_ep);
    cudaEventRecord(ev2, s1);

    // s0: ligand_gather needs g_z (program order) + CSR (ev1)
    cudaStreamWaitEvent(s0, ev1, 0);
    ligand_gather_kernel<<<(N_LIG + 7) / 8, 256, 0, s0>>>(x_ligand, W_tl_r, b_tl_l, W_ep);

    // join: edge_out needs s_l (program order) + s_t (ev2)
    cudaStreamWaitEvent(s0, ev2, 0);
    edge_out_kernel<<<(N_EDGE + 255) / 256, 256, 0, s0>>>(edge_src, edge_dst, b_ep, out);
}

// round 17
// speedup vs baseline: 1.7338x; 1.7338x over previous
#include <cuda_runtime.h>
#include <cuda_bf16.h>
#include <cstdint>

// Problem constants (fixed by the reference)
#define N_LIG   100000
#define N_TGT   20000
#define N_EDGE  250000
#define LIG_IN  4
#define TGT_IN  1280
#define HID     128
#define ZCOLS   256           // [y_t (W_tl_l) | z_r (W_lt_r)]

#define MROWS   96            // M-tile rows (2 x 48)
#define MTILES  209           // ceil(20000 / 96)
#define N_TGT_PAD 20096       // >= 209*96 = 20064

#define SCAN_B 256
#define NBLK ((N_LIG + SCAN_B - 1) / SCAN_B)   // 391

// ---------------- scratch (device globals; no allocation allowed) ----------
__device__ float g_accT[N_TGT * LIG_IN];
__device__ int   g_cntLi[N_LIG];
__device__ int   g_cntTi[N_TGT];
__device__ int   g_offL[N_LIG];
__device__ int   g_woff[N_LIG];
__device__ int   g_part[NBLK];
__device__ int   g_elist[N_EDGE];
__device__ float g_z[(size_t)N_TGT_PAD * ZCOLS];   // fused target projection
__device__ float g_sl[N_LIG];
__device__ float g_st[N_TGT];

// =================== helpers =================================================
static __device__ __forceinline__ uint32_t smem_u32(const void* p) {
    uint32_t a;
    asm("{ .reg .u64 t; cvta.to.shared.u64 t, %1; cvt.u32.u64 %0, t; }"
        : "=r"(a) : "l"(p));
    return a;
}

static __device__ __forceinline__ uint32_t lds32(uint32_t addr) {
    uint32_t v;
    asm volatile("ld.shared.b32 %0, [%1];" : "=r"(v) : "r"(addr));
    return v;
}

static __device__ __forceinline__ uint32_t f2tf32(float f) {
    uint32_t u;
    asm("cvt.rna.tf32.f32 %0, %1;" : "=r"(u) : "f"(f));
    return u;
}

static __device__ __forceinline__ uint32_t u2tf32(uint32_t x) {
    uint32_t u;
    asm("cvt.rna.tf32.f32 %0, %1;" : "=r"(u) : "r"(x));
    return u;
}

static __device__ __forceinline__ void mma_tf32(float* d, const uint32_t* a,
                                                uint32_t b0, uint32_t b1) {
    asm volatile(
        "mma.sync.aligned.m16n8k8.row.col.f32.tf32.tf32.f32 "
        "{%0,%1,%2,%3}, {%4,%5,%6,%7}, {%8,%9}, {%0,%1,%2,%3};"
        : "+f"(d[0]), "+f"(d[1]), "+f"(d[2]), "+f"(d[3])
        : "r"(a[0]), "r"(a[1]), "r"(a[2]), "r"(a[3]), "r"(b0), "r"(b1));
}

static __device__ __forceinline__ void cp16(uint32_t saddr, const void* gaddr) {
    asm volatile("cp.async.cg.shared.global [%0], [%1], 16;"
                 :: "r"(saddr), "l"(gaddr));
}

// ============ edge light pass: degree histograms + target accumulators ======
__global__ __launch_bounds__(256) void edge_light_kernel(
    const int* __restrict__ esrc, const int* __restrict__ edst,
    const float* __restrict__ xlig) {
    int e = blockIdx.x * blockDim.x + threadIdx.x;
    if (e >= N_EDGE) return;
    int s = esrc[e];
    int d = edst[e];
    atomicAdd(&g_cntLi[s], 1);
    atomicAdd(&g_cntTi[d], 1);
    float4 xf = *(const float4*)(xlig + (size_t)s * LIG_IN);
    float* t = g_accT + (size_t)d * LIG_IN;
    atomicAdd(t + 0, xf.x); atomicAdd(t + 1, xf.y);
    atomicAdd(t + 2, xf.z); atomicAdd(t + 3, xf.w);
}

// ============ exclusive scan over g_cntLi -> g_offL (3 kernels) =============
__global__ __launch_bounds__(SCAN_B) void scan1_kernel() {
    __shared__ int sm[SCAN_B];
    int i = blockIdx.x * SCAN_B + threadIdx.x;
    int v = (i < N_LIG) ? g_cntLi[i] : 0;
    sm[threadIdx.x] = v;
    __syncthreads();
    int incl = v;
    #pragma unroll
    for (int o = 1; o < SCAN_B; o <<= 1) {
        int u = (threadIdx.x >= o) ? sm[threadIdx.x - o] : 0;
        __syncthreads();
        incl += u;
        sm[threadIdx.x] = incl;
        __syncthreads();
    }
    if (i < N_LIG) g_offL[i] = incl - v;
    if (threadIdx.x == SCAN_B - 1) g_part[blockIdx.x] = incl;
}

__global__ __launch_bounds__(512) void scan2_kernel() {
    __shared__ int sm[512];
    int t = threadIdx.x;
    int v = (t < NBLK) ? g_part[t] : 0;
    sm[t] = v;
    __syncthreads();
    int incl = v;
    #pragma unroll
    for (int o = 1; o < 512; o <<= 1) {
        int u = (t >= o) ? sm[t - o] : 0;
        __syncthreads();
        incl += u;
        sm[t] = incl;
        __syncthreads();
    }
    if (t < NBLK) g_part[t] = incl - v;   // exclusive
}

__global__ __launch_bounds__(SCAN_B) void scan3_kernel() {
    int i = blockIdx.x * SCAN_B + threadIdx.x;
    if (i >= N_LIG) return;
    int off = g_offL[i] + g_part[blockIdx.x];
    g_offL[i] = off;
    g_woff[i] = off;
}

// ============ fill edge lists ==============================================
__global__ __launch_bounds__(256) void fill_kernel(
    const int* __restrict__ esrc, const int* __restrict__ edst) {
    int e = blockIdx.x * blockDim.x + threadIdx.x;
    if (e >= N_EDGE) return;
    int pos = atomicAdd(&g_woff[esrc[e]], 1);
    g_elist[pos] = edst[e];
}

// ============ TF32 GEMM: z = tf32(x_target) @ tf32(W)^T =====================
// Block 96x128, BK=32, 256 thr, 8 warps (2 m-rows x 4 n-cols), warp 48x32.
// B loaded RAW fp32 straight from W_tl_l / W_lt_r (each [k][128] row-major,
// selected by blockIdx.x); cvt.rna.tf32 applied in the consumer after LDS.
// A+B double-buffered, one __syncthreads per chunk, 2 CTAs/SM. (R12 exact.)
#define GKCH 40                 // 1280 / 32
#define A_PITCH 144
#define A_STRIDE (MROWS * A_PITCH)      // 13824
#define OFF_B (2 * A_STRIDE)            // 27648
#define B_PITCH 544
#define B_STRIDE 17408                  // 32 * 544
#define GSM_TOT (OFF_B + 2 * B_STRIDE)  // 62464

__global__ void __launch_bounds__(256, 2) gemm_tf32_kernel(
    const float* __restrict__ X,
    const float* __restrict__ Wl,       // W_tl_l [k][128]
    const float* __restrict__ Wr) {     // W_lt_r [k][128]
    extern __shared__ char smem[];
    const uint32_t sb = smem_u32(smem);
    const int tid = threadIdx.x;
    const int lane = tid & 31;
    const int wid = tid >> 5;
    const int warpRow = wid & 1;      // m: 2 x 48
    const int warpCol = wid >> 1;     // n: 4 x 32

    // ---- A producer: threads 0..191, 2 threads per row, 16 floats each ----
    const bool aact = tid < 2 * MROWS;
    const int arow = tid >> 1;
    const int ahalf = tid & 1;
    const long growA = (long)blockIdx.y * MROWS + arow;
    const bool aval = aact && (growA < N_TGT);
    const float* aptr = X + (size_t)(aval ? growA : 0) * TGT_IN + ahalf * 16;
    const uint32_t a_sts = (uint32_t)(arow * A_PITCH + ahalf * 64);

    // ---- B producer: 8 threads per k-row, 4x cp16 each, raw fp32 W ----
    const float* Wsel = (blockIdx.x == 0) ? Wl : Wr;
    const int bk = tid >> 3;          // 0..31
    const int bseg = tid & 7;
    const float* bptr = Wsel + (size_t)bk * HID + bseg * 4;
    const uint32_t b_sts = (uint32_t)(bk * B_PITCH + bseg * 16);

    // ---- consumer fragment base offsets ----
    const uint32_t a_frag =
        (uint32_t)((warpRow * 48 + (lane >> 2)) * A_PITCH + (lane & 3) * 4);
    const uint32_t b_frag =
        (uint32_t)((lane & 3) * B_PITCH + (warpCol * 32 + (lane >> 2)) * 4);

    float acc[3][4][4];
    #pragma unroll
    for (int i = 0; i < 3; i++)
        #pragma unroll
        for (int j = 0; j < 4; j++)
            #pragma unroll
            for (int q = 0; q < 4; q++) acc[i][j][q] = 0.f;

    float4 apre[4];

    auto storeA = [&](int buf) {
        float f[16] = {apre[0].x, apre[0].y, apre[0].z, apre[0].w,
                       apre[1].x, apre[1].y, apre[1].z, apre[1].w,
                       apre[2].x, apre[2].y, apre[2].z, apre[2].w,
                       apre[3].x, apre[3].y, apre[3].z, apre[3].w};
        uint32_t u[16];
        #pragma unroll
        for (int j = 0; j < 16; j++) u[j] = f2tf32(f[j]);
        char* base = smem + buf * A_STRIDE + a_sts;
        #pragma unroll
        for (int j = 0; j < 4; j++)
            *(uint4*)(base + j * 16) =
                make_uint4(u[4 * j], u[4 * j + 1], u[4 * j + 2], u[4 * j + 3]);
    };

    // ---------- prologue: chunk 0 ----------
    {
        uint32_t s0 = sb + OFF_B;
        #pragma unroll
        for (int j = 0; j < 4; j++)
            cp16(s0 + b_sts + j * 128, bptr + j * 32);
        asm volatile("cp.async.commit_group;");
        if (aval) {
            #pragma unroll
            for (int i = 0; i < 4; i++)
                apre[i] = *(const float4*)(aptr + i * 4);
        } else {
            #pragma unroll
            for (int i = 0; i < 4; i++) apre[i] = make_float4(0.f, 0.f, 0.f, 0.f);
        }
        if (aact) storeA(0);
        asm volatile("cp.async.wait_group 0;");
        __syncthreads();
    }

    // ---------- main loop: one sync per chunk ----------
    for (int c = 0; c < GKCH; c++) {
        const bool more = (c + 1) < GKCH;
        if (more) {
            uint32_t snext = sb + OFF_B + ((c + 1) & 1) * B_STRIDE;
            const float* b2 = bptr + (size_t)(c + 1) * 32 * HID;
            #pragma unroll
            for (int j = 0; j < 4; j++)
                cp16(snext + b_sts + j * 128, b2 + j * 32);
            asm volatile("cp.async.commit_group;");
            if (aval) {
                #pragma unroll
                for (int i = 0; i < 4; i++)
                    apre[i] = *(const float4*)(aptr + (c + 1) * 32 + i * 4);
            }
        }

        // ---- compute on chunk c ----
        {
            const uint32_t ab = sb + (c & 1) * A_STRIDE;
            const uint32_t bb = sb + OFF_B + (c & 1) * B_STRIDE;
            #pragma unroll
            for (int ks = 0; ks < 4; ks++) {
                uint32_t b0[4], b1[4];
                #pragma unroll
                for (int nt = 0; nt < 4; nt++) {
                    uint32_t ad = bb + b_frag + ks * (8 * B_PITCH) + nt * 32;
                    b0[nt] = u2tf32(lds32(ad));                  // cvt fused here
                    b1[nt] = u2tf32(lds32(ad + 4 * B_PITCH));
                }
                #pragma unroll
                for (int mt = 0; mt < 3; mt++) {
                    uint32_t aa = ab + a_frag + mt * (16 * A_PITCH) + ks * 32;
                    uint32_t a[4];
                    a[0] = lds32(aa);
                    a[1] = lds32(aa + 8 * A_PITCH);
                    a[2] = lds32(aa + 16);
                    a[3] = lds32(aa + 8 * A_PITCH + 16);
                    #pragma unroll
                    for (int nt = 0; nt < 4; nt++)
                        mma_tf32(acc[mt][nt], a, b0[nt], b1[nt]);
                }
            }
        }

        if (more) {
            if (aact) storeA((c + 1) & 1);       // writes the OTHER A buffer
            asm volatile("cp.async.wait_group 0;");
        }
        __syncthreads();
    }

    // ---------- epilogue: write fp32 accumulators to g_z ----------
    const int rbase = blockIdx.y * MROWS + warpRow * 48;
    const int cbase = blockIdx.x * 128 + warpCol * 32;
    #pragma unroll
    for (int mt = 0; mt < 3; mt++) {
        #pragma unroll
        for (int nt = 0; nt < 4; nt++) {
            int r0 = rbase + mt * 16 + (lane >> 2);
            int cc = cbase + nt * 8 + (lane & 3) * 2;
            *(float2*)(g_z + (size_t)r0 * ZCOLS + cc) =
                make_float2(acc[mt][nt][0], acc[mt][nt][1]);
            *(float2*)(g_z + (size_t)(r0 + 8) * ZCOLS + cc) =
                make_float2(acc[mt][nt][2], acc[mt][nt][3]);
        }
    }
}

// ---------------- target finalize: s_t[t] = <relu(t_out), W_ep[128:256]> ---
__global__ __launch_bounds__(256) void target_final_kernel(
    const float* __restrict__ W_lt_l, const float* __restrict__ b_lt_l,
    const float* __restrict__ W_ep) {
    int t = blockIdx.x * (blockDim.x >> 5) + (threadIdx.x >> 5);
    int lane = threadIdx.x & 31;
    if (t >= N_TGT) return;
    float inv = 1.f / fmaxf((float)g_cntTi[t], 1.f);
    float m0 = g_accT[t * 4 + 0] * inv;
    float m1 = g_accT[t * 4 + 1] * inv;
    float m2 = g_accT[t * 4 + 2] * inv;
    float m3 = g_accT[t * 4 + 3] * inv;
    float sum = 0.f;
    #pragma unroll
    for (int i = 0; i < 4; i++) {
        int h = lane + 32 * i;
        float v = b_lt_l[h] + g_z[(size_t)t * ZCOLS + HID + h];
        v = fmaf(m0, W_lt_l[0 * HID + h], v);
        v = fmaf(m1, W_lt_l[1 * HID + h], v);
        v = fmaf(m2, W_lt_l[2 * HID + h], v);
        v = fmaf(m3, W_lt_l[3 * HID + h], v);
        v = fmaxf(v, 0.f);
        sum = fmaf(v, W_ep[HID + h], sum);
    }
    #pragma unroll
    for (int o = 16; o > 0; o >>= 1) sum += __shfl_xor_sync(0xffffffffu, sum, o);
    if (lane == 0) g_st[t] = sum;
}

// ---------------- ligand gather + finalize (warp per ligand) ----------------
// Software-pipelined: next edge's dst index loads while current y row sums.
__global__ __launch_bounds__(256) void ligand_gather_kernel(
    const float* __restrict__ xlig, const float* __restrict__ W_tl_r,
    const float* __restrict__ b_tl_l, const float* __restrict__ W_ep) {
    int l = blockIdx.x * (blockDim.x >> 5) + (threadIdx.x >> 5);
    int lane = threadIdx.x & 31;
    if (l >= N_LIG) return;
    int start = g_offL[l];
    int cnt = g_cntLi[l];
    float4 acc = make_float4(0.f, 0.f, 0.f, 0.f);
    int dnext = (cnt > 0) ? g_elist[start] : 0;
    for (int i = 0; i < cnt; i++) {
        int d = dnext;
        if (i + 1 < cnt) dnext = g_elist[start + i + 1];
        float4 y = *((const float4*)(g_z + (size_t)d * ZCOLS) + lane);
        acc.x += y.x; acc.y += y.y; acc.z += y.z; acc.w += y.w;
    }
    float inv = 1.f / fmaxf((float)cnt, 1.f);
    float4 xf = *(const float4*)(xlig + (size_t)l * LIG_IN);
    float m[4] = {acc.x * inv, acc.y * inv, acc.z * inv, acc.w * inv};
    float sum = 0.f;
    #pragma unroll
    for (int j = 0; j < 4; j++) {
        int h = lane * 4 + j;
        float v = b_tl_l[h] + m[j];
        v = fmaf(xf.x, W_tl_r[0 * HID + h], v);
        v = fmaf(xf.y, W_tl_r[1 * HID + h], v);
        v = fmaf(xf.z, W_tl_r[2 * HID + h], v);
        v = fmaf(xf.w, W_tl_r[3 * HID + h], v);
        v = fmaxf(v, 0.f);
        sum = fmaf(v, W_ep[h], sum);
    }
    #pragma unroll
    for (int o = 16; o > 0; o >>= 1) sum += __shfl_xor_sync(0xffffffffu, sum, o);
    if (lane == 0) g_sl[l] = sum;
}

// ---------------- edge output ------------------------------------------------
__global__ __launch_bounds__(512) void edge_out_kernel(
    const int* __restrict__ esrc, const int* __restrict__ edst,
    const float* __restrict__ b_ep, float* __restrict__ out) {
    int e = blockIdx.x * blockDim.x + threadIdx.x;
    if (e >= N_EDGE) return;
    out[e] = g_sl[esrc[e]] + g_st[edst[e]] + __ldg(b_ep);
}

// ---------------- launch: fork/join across two streams ----------------------
extern "C" void kernel_launch(void* const* d_in, const int* in_sizes, int n_in,
                              void* d_out, int out_size) {
    const float* x_ligand = (const float*)d_in[0];
    const float* x_target = (const float*)d_in[1];
    const int*   edge_src = (const int*)d_in[2];
    const int*   edge_dst = (const int*)d_in[3];
    const float* W_lt_l   = (const float*)d_in[4];
    const float* b_lt_l   = (const float*)d_in[5];
    const float* W_lt_r   = (const float*)d_in[6];
    const float* W_tl_l   = (const float*)d_in[7];
    const float* b_tl_l   = (const float*)d_in[8];
    const float* W_tl_r   = (const float*)d_in[9];
    const float* W_ep     = (const float*)d_in[10];
    const float* b_ep     = (const float*)d_in[11];
    float* out = (float*)d_out;

    // one-time host resources (streams/events are not device memory)
    static cudaStream_t s1 = nullptr;
    static cudaEvent_t evRoot = nullptr, evG = nullptr, ev1 = nullptr, ev2 = nullptr;
    if (!s1) {
        cudaStreamCreateWithFlags(&s1, cudaStreamNonBlocking);
        cudaEventCreateWithFlags(&evRoot, cudaEventDisableTiming);
        cudaEventCreateWithFlags(&evG, cudaEventDisableTiming);
        cudaEventCreateWithFlags(&ev1, cudaEventDisableTiming);
        cudaEventCreateWithFlags(&ev2, cudaEventDisableTiming);
    }
    cudaStream_t s0 = 0;   // capturing (legacy) stream

    // ---- fork s1 off the captured stream ----
    cudaEventRecord(evRoot, s0);
    cudaStreamWaitEvent(s1, evRoot, 0);

    // ---- s1: memsets + edge-prep head ----
    {
        void *pAccT, *pCntLi, *pCntTi;
        cudaGetSymbolAddress(&pAccT, g_accT);
        cudaGetSymbolAddress(&pCntLi, g_cntLi);
        cudaGetSymbolAddress(&pCntTi, g_cntTi);
        cudaMemsetAsync(pAccT, 0, (size_t)N_TGT * LIG_IN * sizeof(float), s1);
        cudaMemsetAsync(pCntLi, 0, (size_t)N_LIG * sizeof(int), s1);
        cudaMemsetAsync(pCntTi, 0, (size_t)N_TGT * sizeof(int), s1);
    }

    // s0: GEMM launches immediately (W conversion fused into it)
    edge_light_kernel<<<(N_EDGE + 255) / 256, 256, 0, s1>>>(edge_src, edge_dst, x_ligand);
    {
        cudaFuncSetAttribute(gemm_tf32_kernel,
                             cudaFuncAttributeMaxDynamicSharedMemorySize, GSM_TOT);
        dim3 grid(2, MTILES);
        gemm_tf32_kernel<<<grid, 256, GSM_TOT, s0>>>(x_target, W_tl_l, W_lt_r);
    }
    cudaEventRecord(evG, s0);       // g_z ready

    // ---- s1: rest of CSR pipeline (concurrent with GEMM) ----
    scan1_kernel<<<NBLK, SCAN_B, 0, s1>>>();
    scan2_kernel<<<1, 512, 0, s1>>>();
    scan3_kernel<<<NBLK, SCAN_B, 0, s1>>>();
    fill_kernel<<<(N_EDGE + 255) / 256, 256, 0, s1>>>(edge_src, edge_dst);
    cudaEventRecord(ev1, s1);       // CSR + accT ready

    // s1: target_final needs g_z (evG) and its own accT (program order)
    cudaStreamWaitEvent(s1, evG, 0);
    target_final_kernel<<<(N_TGT + 7) / 8, 256, 0, s1>>>(W_lt_l, b_lt_l, W_ep);
    cudaEventRecord(ev2, s1);

    // s0: ligand_gather needs g_z (program order) + CSR (ev1)
    cudaStreamWaitEvent(s0, ev1, 0);
    ligand_gather_kernel<<<(N_LIG + 7) / 8, 256, 0, s0>>>(x_ligand, W_tl_r, b_tl_l, W_ep);

    // join: edge_out needs s_l (program order) + s_t (ev2)
    cudaStreamWaitEvent(s0, ev2, 0);
    edge_out_kernel<<<(N_EDGE + 511) / 512, 512, 0, s0>>>(edge_src, edge_dst, b_ep, out);
}